// round 15
// baseline (speedup 1.0000x reference)
#include <cuda_runtime.h>
#include <cuda_bf16.h>
#include <cstdint>

// Problem shape (fixed): x [4,2048,4096] -> M=8192, K=4096; W [4096,4096] (out,in)
#define M_DIM 8192
#define N_DIM 4096
#define K_DIM 4096

// ---------------- device scratch ----------------
// g_mm: four atomicMax slots, initialized to 0 by cudaMemsetAsync.
//   slot0 = max(~f2ord(x_min)), slot1 = max(f2ord(x_max)), slots 2/3 for W.
__device__ unsigned int g_mm[4];
__device__ __nv_bfloat16 g_qx[(size_t)M_DIM * K_DIM];    // 64 MB
__device__ __nv_bfloat16 g_qw[(size_t)N_DIM * K_DIM];    // 32 MB
__device__ float g_cm[M_DIM];                            // s*(K*zx*zw - zw*rsx[m])
__device__ float g_cn[N_DIM];                            // bias[n] - s*zx*rsw[n]

// ---------------- PTX helpers (arch-neutral, sm_80+) ----------------
__device__ __forceinline__ uint32_t smem_u32(const void* p) {
    uint32_t a;
    asm("{ .reg .u64 t; cvta.to.shared.u64 t, %1; cvt.u32.u64 %0, t; }" : "=r"(a) : "l"(p));
    return a;
}
#define CP_ASYNC16(dst, src) \
    asm volatile("cp.async.cg.shared.global [%0], [%1], 16;" :: "r"(dst), "l"(src) : "memory")
#define CP_COMMIT() asm volatile("cp.async.commit_group;" ::: "memory")

#define LDM_X4(r0, r1, r2, r3, addr) \
    asm volatile("ldmatrix.sync.aligned.m8n8.x4.shared.b16 {%0,%1,%2,%3}, [%4];" \
        : "=r"(r0), "=r"(r1), "=r"(r2), "=r"(r3) : "r"(addr))

#define MMA_BF16(c, a, b0, b1) \
    asm volatile("mma.sync.aligned.m16n8k16.row.col.f32.bf16.bf16.f32 " \
        "{%0,%1,%2,%3}, {%4,%5,%6,%7}, {%8,%9}, {%0,%1,%2,%3};" \
        : "+f"((c)[0]), "+f"((c)[1]), "+f"((c)[2]), "+f"((c)[3]) \
        : "r"((a)[0]), "r"((a)[1]), "r"((a)[2]), "r"((a)[3]), "r"(b0), "r"(b1))

// ---------------- order-preserving encode ----------------
__device__ __forceinline__ unsigned f2ord(float f) {
    unsigned u = __float_as_uint(f);
    return (u & 0x80000000u) ? ~u : (u | 0x80000000u);
}
__device__ __forceinline__ float ord2f(unsigned u) {
    unsigned b = (u & 0x80000000u) ? (u ^ 0x80000000u) : ~u;
    return __uint_as_float(b);
}

// Recompute quantization params from g_mm — identical IEEE fp32 sequence in
// every caller -> identical (deterministic) values everywhere.
struct QParams { float sx, zx, sw, zw; };
__device__ __forceinline__ QParams qparams_from_mm() {
    QParams q;
    float xmn = ord2f(~g_mm[0]), xmx = ord2f(g_mm[1]);
    float wmn = ord2f(~g_mm[2]), wmx = ord2f(g_mm[3]);
    q.sx = (xmx - xmn) / 255.0f;
    q.zx = rintf(-128.0f - xmn / q.sx);
    q.sw = (wmx - wmn) / 255.0f;
    q.zw = rintf(-128.0f - wmn / q.sw);
    return q;
}

// One launch covering both tensors: blocks [0,2048) -> x, [2048,3072) -> W
__global__ void minmax2_kernel(const float* __restrict__ xp, const float* __restrict__ wp) {
    const int isW = (blockIdx.x >= 2048);
    const float4* p4 = (const float4*)(isW ? wp : xp);
    const int n4 = (isW ? (N_DIM * K_DIM) : (M_DIM * K_DIM)) >> 2;
    const int nb = isW ? 1024 : 2048;
    const int bix = isW ? (blockIdx.x - 2048) : blockIdx.x;
    const int slot = isW ? 2 : 0;

    float mn = 3.4e38f, mx = -3.4e38f;
    int idx = bix * blockDim.x + threadIdx.x;
    int stride = nb * blockDim.x;
    for (int i = idx; i < n4; i += stride) {
        float4 v = p4[i];
        mn = fminf(mn, fminf(fminf(v.x, v.y), fminf(v.z, v.w)));
        mx = fmaxf(mx, fmaxf(fmaxf(v.x, v.y), fmaxf(v.z, v.w)));
    }
    #pragma unroll
    for (int o = 16; o; o >>= 1) {
        mn = fminf(mn, __shfl_xor_sync(0xFFFFFFFFu, mn, o));
        mx = fmaxf(mx, __shfl_xor_sync(0xFFFFFFFFu, mx, o));
    }
    __shared__ float smn[8], smx[8];
    int lane = threadIdx.x & 31, wid = threadIdx.x >> 5;
    if (lane == 0) { smn[wid] = mn; smx[wid] = mx; }
    __syncthreads();
    if (wid == 0) {
        mn = (lane < (blockDim.x >> 5)) ? smn[lane] : 3.4e38f;
        mx = (lane < (blockDim.x >> 5)) ? smx[lane] : -3.4e38f;
        #pragma unroll
        for (int o = 4; o; o >>= 1) {
            mn = fminf(mn, __shfl_xor_sync(0xFFFFFFFFu, mn, o));
            mx = fmaxf(mx, __shfl_xor_sync(0xFFFFFFFFu, mx, o));
        }
        if (lane == 0) {
            atomicMax(&g_mm[slot],     ~f2ord(mn));
            atomicMax(&g_mm[slot + 1],  f2ord(mx));
        }
    }
}

// quantize fp32 -> bf16-exact integer; per-row integer sum folded directly into
// the per-row correction term (corr kernel eliminated).
//   x row m:  g_cm[m] = s*(K*zx*zw - zw*rsx[m])        (fp64, cast fp32)
//   W row n:  g_cn[n] = bias[n] - s*zx*rsw[n]          (fp64, cast fp32)
__global__ __launch_bounds__(256) void quant_all_kernel(const float* __restrict__ xp,
                                                        const float* __restrict__ wp,
                                                        const float* __restrict__ bias) {
    const QParams qp = qparams_from_mm();
    const int which = (blockIdx.x >= M_DIM);
    const int row = which ? (blockIdx.x - M_DIM) : blockIdx.x;
    const float rs = which ? (1.0f / qp.sw) : (1.0f / qp.sx);
    const float z  = which ? qp.zw : qp.zx;
    const float* src = which ? wp : xp;
    __nv_bfloat16* dst = which ? g_qw : g_qx;

    const float4* src4 = (const float4*)(src + (size_t)row * K_DIM);
    __nv_bfloat162* d2 = (__nv_bfloat162*)(dst + (size_t)row * K_DIM);
    int acc = 0;
    #pragma unroll
    for (int it = 0; it < 4; it++) {
        const int j = threadIdx.x + it * 256;
        float4 v = src4[j];
        float q0 = fminf(fmaxf(rintf(v.x * rs) + z, -128.0f), 127.0f);
        float q1 = fminf(fmaxf(rintf(v.y * rs) + z, -128.0f), 127.0f);
        float q2 = fminf(fmaxf(rintf(v.z * rs) + z, -128.0f), 127.0f);
        float q3 = fminf(fmaxf(rintf(v.w * rs) + z, -128.0f), 127.0f);
        acc += (int)q0 + (int)q1 + (int)q2 + (int)q3;
        __nv_bfloat162 ab, cd;
        ab.x = __float2bfloat16(q0); ab.y = __float2bfloat16(q1);
        cd.x = __float2bfloat16(q2); cd.y = __float2bfloat16(q3);
        d2[j * 2]     = ab;
        d2[j * 2 + 1] = cd;
    }
    #pragma unroll
    for (int o = 16; o; o >>= 1) acc += __shfl_xor_sync(0xFFFFFFFFu, acc, o);
    __shared__ int sacc[8];
    int lane = threadIdx.x & 31, wid = threadIdx.x >> 5;
    if (lane == 0) sacc[wid] = acc;
    __syncthreads();
    if (wid == 0) {
        acc = (lane < 8) ? sacc[lane] : 0;
        #pragma unroll
        for (int o = 4; o; o >>= 1) acc += __shfl_xor_sync(0xFFFFFFFFu, acc, o);
        if (lane == 0) {
            const double sd  = (double)(qp.sx * qp.sw);
            if (which) {
                g_cn[row] = (float)((double)bias[row]
                            - sd * (double)qp.zx * (double)acc);
            } else {
                const double kzz = (double)qp.zx * (double)qp.zw * (double)K_DIM;
                g_cm[row] = (float)(sd * (kzz - (double)qp.zw * (double)acc));
            }
        }
    }
}

// ============================================================================
// bf16 HMMA GEMM (R12 config — best known): CTA tile 128x256, BK=128 (256B rows).
// 16 warps (512 thr): 2 (M) x 8 (N), warp tile 64x32. 2-stage cp.async ring.
// ROWB=272: stride = 68 words = 4 (mod 32) -> conflict-free ldmatrix.
// ============================================================================
#define ROWB   272
#define TILE_A (128 * ROWB)                 // 34816
#define TILE_B (256 * ROWB)                 // 69632
#define STAGEB (TILE_A + TILE_B)            // 104448
#define GEMM_SMEM (2 * STAGEB)              // 208896
#define NKT (K_DIM / 128)                   // 32

__device__ __forceinline__ void fill_stage(uint32_t sbase,
                                           const char* __restrict__ Agc,
                                           const char* __restrict__ Bgc,
                                           int kt, int tid) {
    const int kOffB = kt * 256;
    const int rowStride = K_DIM * 2;
    // A: 128 rows x 16 chunks = 2048 -> 4 per thread
    #pragma unroll
    for (int i = 0; i < 4; i++) {
        const int ch = tid + i * 512;
        const int row = ch >> 4, c = (ch & 15) * 16;
        unsigned long long src = __cvta_generic_to_global(Agc + (size_t)row * rowStride + kOffB + c);
        CP_ASYNC16(sbase + row * ROWB + c, src);
    }
    // B: 256 rows x 16 chunks = 4096 -> 8 per thread
    #pragma unroll
    for (int i = 0; i < 8; i++) {
        const int ch = tid + i * 512;
        const int row = ch >> 4, c = (ch & 15) * 16;
        unsigned long long src = __cvta_generic_to_global(Bgc + (size_t)row * rowStride + kOffB + c);
        CP_ASYNC16(sbase + TILE_A + row * ROWB + c, src);
    }
}

__global__ __launch_bounds__(512, 1) void gemm_bf16_kernel(float* __restrict__ out) {
    extern __shared__ char smem[];
    const uint32_t sm = smem_u32(smem);
    const int tid = threadIdx.x;
    const int wid = tid >> 5, lane = tid & 31;
    const int warp_m = wid & 1;     // 2 warps over M: 64 rows each
    const int warp_n = wid >> 1;    // 8 warps over N: 32 cols each

    const int m0 = blockIdx.y * 128;
    const int n0 = blockIdx.x * 256;
    const char* Agc = (const char*)(g_qx + (size_t)m0 * K_DIM);
    const char* Bgc = (const char*)(g_qw + (size_t)n0 * K_DIM);

    const int l7 = lane & 7;
    const uint32_t a_lane = (uint32_t)((l7 + ((lane >> 3) & 1) * 8) * ROWB + ((lane >> 4) << 4));
    const uint32_t b_lane = (uint32_t)((l7 + ((lane >> 4) & 1) * 8) * ROWB + (((lane >> 3) & 1) << 4));

    float c[4][4][4];
    #pragma unroll
    for (int i = 0; i < 4; i++)
        #pragma unroll
        for (int j = 0; j < 4; j++)
            #pragma unroll
            for (int e = 0; e < 4; e++) c[i][j][e] = 0.0f;

    fill_stage(sm, Agc, Bgc, 0, tid);
    CP_COMMIT();

    for (int kt = 0; kt < NKT; kt++) {
        const int cs = kt & 1;
        asm volatile("cp.async.wait_group 0;" ::: "memory");   // only G_kt pending here
        __syncthreads();    // compute(kt-1) done on stage cs^1 + stage cs data visible

        if (kt + 1 < NKT) {
            fill_stage(sm + (cs ^ 1) * STAGEB, Agc, Bgc, kt + 1, tid);
            CP_COMMIT();    // overlaps with compute below
        }

        const uint32_t sb = sm + cs * STAGEB;
        const uint32_t aT = sb + (uint32_t)(warp_m * 64) * ROWB + a_lane;
        const uint32_t bT = sb + TILE_A + (uint32_t)(warp_n * 32) * ROWB + b_lane;

        #pragma unroll
        for (int ks = 0; ks < 8; ks++) {
            uint32_t a[4][4];
            #pragma unroll
            for (int mf = 0; mf < 4; mf++)
                LDM_X4(a[mf][0], a[mf][1], a[mf][2], a[mf][3],
                       aT + (uint32_t)(mf * 16) * ROWB + ks * 32);
            uint32_t b[2][4];
            #pragma unroll
            for (int nb = 0; nb < 2; nb++)
                LDM_X4(b[nb][0], b[nb][1], b[nb][2], b[nb][3],
                       bT + (uint32_t)(nb * 16) * ROWB + ks * 32);
            #pragma unroll
            for (int mf = 0; mf < 4; mf++)
                #pragma unroll
                for (int nb = 0; nb < 2; nb++) {
                    MMA_BF16(c[mf][nb * 2],     a[mf], b[nb][0], b[nb][1]);
                    MMA_BF16(c[mf][nb * 2 + 1], a[mf], b[nb][2], b[nb][3]);
                }
        }
    }

    // ---------------- fp32 epilogue: out = s*acc + corrM[m] + corrN[n] ----------------
    const QParams qp = qparams_from_mm();
    const float s_sc = qp.sx * qp.sw;
    const int g  = lane >> 2;
    const int t2 = (lane & 3) * 2;

    #pragma unroll
    for (int mf = 0; mf < 4; mf++) {
        const int gm0 = m0 + warp_m * 64 + mf * 16 + g;
        const float cm0 = g_cm[gm0];
        const float cm1 = g_cm[gm0 + 8];
        float* r0 = out + (size_t)gm0 * N_DIM;
        float* r1 = out + (size_t)(gm0 + 8) * N_DIM;
        #pragma unroll
        for (int nf = 0; nf < 4; nf++) {
            const int gn = n0 + warp_n * 32 + nf * 8 + t2;
            const float2 cn = *(const float2*)&g_cn[gn];
            float2 o;
            o.x = fmaf(s_sc, c[mf][nf][0], cm0 + cn.x);
            o.y = fmaf(s_sc, c[mf][nf][1], cm0 + cn.y);
            *(float2*)(r0 + gn) = o;
            o.x = fmaf(s_sc, c[mf][nf][2], cm1 + cn.x);
            o.y = fmaf(s_sc, c[mf][nf][3], cm1 + cn.y);
            *(float2*)(r1 + gn) = o;
        }
    }
}

// ---------------- launch ----------------
extern "C" void kernel_launch(void* const* d_in, const int* in_sizes, int n_in,
                              void* d_out, int out_size) {
    const float* x    = (const float*)d_in[0];
    const float* W    = (const float*)d_in[1];
    const float* bias = (const float*)d_in[2];
    float* out = (float*)d_out;

    static void* mm_addr = nullptr;
    if (!mm_addr) {
        cudaFuncSetAttribute(gemm_bf16_kernel, cudaFuncAttributeMaxDynamicSharedMemorySize, GEMM_SMEM);
        cudaGetSymbolAddress(&mm_addr, g_mm);
    }

    cudaMemsetAsync(mm_addr, 0, 16);               // all 4 slots -> 0 (atomicMax targets)
    minmax2_kernel<<<3072, 256>>>(x, W);
    quant_all_kernel<<<M_DIM + N_DIM, 256>>>(x, W, bias);

    dim3 grid(N_DIM / 256, M_DIM / 128);   // 16 x 64 = 1024 CTAs
    gemm_bf16_kernel<<<grid, 512, GEMM_SMEM>>>(out);
}

// round 16
// speedup vs baseline: 1.0233x; 1.0233x over previous
#include <cuda_runtime.h>
#include <cuda_bf16.h>
#include <cstdint>

// Problem shape (fixed): x [4,2048,4096] -> M=8192, K=4096; W [4096,4096] (out,in)
#define M_DIM 8192
#define N_DIM 4096
#define K_DIM 4096

// ---------------- device scratch ----------------
// g_mm: all four slots are atomicMax targets initialized to 0 by cudaMemsetAsync.
//   slot0 = max(~f2ord(x_min-cand)), slot1 = max(f2ord(x_max-cand)), slots 2/3 for W.
__device__ unsigned int g_mm[4];
__device__ float  g_qp[8];                               // sx, zx, sw, zw, s, invsx, invsw
__device__ double g_kzz;
__device__ __nv_bfloat16 g_qx[(size_t)M_DIM * K_DIM];    // 64 MB
__device__ __nv_bfloat16 g_qw[(size_t)N_DIM * K_DIM];    // 32 MB
__device__ int g_rsx[M_DIM];
__device__ int g_rsw[N_DIM];
__device__ float g_cm[M_DIM];                            // s*(K*zx*zw - zw*rsx[m])
__device__ float g_cn[N_DIM];                            // bias[n] - s*zx*rsw[n]

// ---------------- PTX helpers (arch-neutral, sm_80+) ----------------
__device__ __forceinline__ uint32_t smem_u32(const void* p) {
    uint32_t a;
    asm("{ .reg .u64 t; cvta.to.shared.u64 t, %1; cvt.u32.u64 %0, t; }" : "=r"(a) : "l"(p));
    return a;
}
#define CP_ASYNC16(dst, src) \
    asm volatile("cp.async.cg.shared.global [%0], [%1], 16;" :: "r"(dst), "l"(src) : "memory")
#define CP_COMMIT() asm volatile("cp.async.commit_group;" ::: "memory")

#define LDM_X4(r0, r1, r2, r3, addr) \
    asm volatile("ldmatrix.sync.aligned.m8n8.x4.shared.b16 {%0,%1,%2,%3}, [%4];" \
        : "=r"(r0), "=r"(r1), "=r"(r2), "=r"(r3) : "r"(addr))

#define MMA_BF16(c, a, b0, b1) \
    asm volatile("mma.sync.aligned.m16n8k16.row.col.f32.bf16.bf16.f32 " \
        "{%0,%1,%2,%3}, {%4,%5,%6,%7}, {%8,%9}, {%0,%1,%2,%3};" \
        : "+f"((c)[0]), "+f"((c)[1]), "+f"((c)[2]), "+f"((c)[3]) \
        : "r"((a)[0]), "r"((a)[1]), "r"((a)[2]), "r"((a)[3]), "r"(b0), "r"(b1))

// ---------------- order-preserving encode ----------------
__device__ __forceinline__ unsigned f2ord(float f) {
    unsigned u = __float_as_uint(f);
    return (u & 0x80000000u) ? ~u : (u | 0x80000000u);
}
__device__ __forceinline__ float ord2f(unsigned u) {
    unsigned b = (u & 0x80000000u) ? (u ^ 0x80000000u) : ~u;
    return __uint_as_float(b);
}

// One launch covering both tensors: blocks [0,2048) -> x, [2048,3072) -> W
// min tracked as atomicMax of ~f2ord(v): all slots init to 0 via memset.
__global__ void minmax2_kernel(const float* __restrict__ xp, const float* __restrict__ wp) {
    const int isW = (blockIdx.x >= 2048);
    const float4* p4 = (const float4*)(isW ? wp : xp);
    const int n4 = (isW ? (N_DIM * K_DIM) : (M_DIM * K_DIM)) >> 2;
    const int nb = isW ? 1024 : 2048;
    const int bix = isW ? (blockIdx.x - 2048) : blockIdx.x;
    const int slot = isW ? 2 : 0;

    float mn = 3.4e38f, mx = -3.4e38f;
    int idx = bix * blockDim.x + threadIdx.x;
    int stride = nb * blockDim.x;
    for (int i = idx; i < n4; i += stride) {
        float4 v = p4[i];
        mn = fminf(mn, fminf(fminf(v.x, v.y), fminf(v.z, v.w)));
        mx = fmaxf(mx, fmaxf(fmaxf(v.x, v.y), fmaxf(v.z, v.w)));
    }
    #pragma unroll
    for (int o = 16; o; o >>= 1) {
        mn = fminf(mn, __shfl_xor_sync(0xFFFFFFFFu, mn, o));
        mx = fmaxf(mx, __shfl_xor_sync(0xFFFFFFFFu, mx, o));
    }
    __shared__ float smn[8], smx[8];
    int lane = threadIdx.x & 31, wid = threadIdx.x >> 5;
    if (lane == 0) { smn[wid] = mn; smx[wid] = mx; }
    __syncthreads();
    if (wid == 0) {
        mn = (lane < (blockDim.x >> 5)) ? smn[lane] : 3.4e38f;
        mx = (lane < (blockDim.x >> 5)) ? smx[lane] : -3.4e38f;
        #pragma unroll
        for (int o = 4; o; o >>= 1) {
            mn = fminf(mn, __shfl_xor_sync(0xFFFFFFFFu, mn, o));
            mx = fmaxf(mx, __shfl_xor_sync(0xFFFFFFFFu, mx, o));
        }
        if (lane == 0) {
            atomicMax(&g_mm[slot],     ~f2ord(mn));
            atomicMax(&g_mm[slot + 1],  f2ord(mx));
        }
    }
}

__global__ void scales_kernel() {
    if (threadIdx.x == 0) {
        float xmn = ord2f(~g_mm[0]), xmx = ord2f(g_mm[1]);
        float wmn = ord2f(~g_mm[2]), wmx = ord2f(g_mm[3]);
        float sx = (xmx - xmn) / 255.0f;
        float zx = rintf(-128.0f - xmn / sx);
        float sw = (wmx - wmn) / 255.0f;
        float zw = rintf(-128.0f - wmn / sw);
        g_qp[0] = sx; g_qp[1] = zx; g_qp[2] = sw; g_qp[3] = zw;
        g_qp[4] = sx * sw;
        g_qp[5] = 1.0f / sx;
        g_qp[6] = 1.0f / sw;
        g_kzz = (double)zx * (double)zw * (double)K_DIM;
    }
}

// quantize fp32 -> bf16-exact integer + per-row integer sum; both tensors in one launch.
// 256 threads/block, K=4096 -> exactly 4 unrolled float4 iterations per thread.
__global__ __launch_bounds__(256) void quant_all_kernel(const float* __restrict__ xp,
                                                        const float* __restrict__ wp) {
    const int which = (blockIdx.x >= M_DIM);
    const int row = which ? (blockIdx.x - M_DIM) : blockIdx.x;
    const float rs = g_qp[which ? 6 : 5];
    const float z  = g_qp[which ? 3 : 1];
    const float* src = which ? wp : xp;
    __nv_bfloat16* dst = which ? g_qw : g_qx;
    int* rsum = which ? g_rsw : g_rsx;

    const float4* src4 = (const float4*)(src + (size_t)row * K_DIM);
    __nv_bfloat162* d2 = (__nv_bfloat162*)(dst + (size_t)row * K_DIM);
    int acc = 0;
    #pragma unroll
    for (int it = 0; it < 4; it++) {
        const int j = threadIdx.x + it * 256;
        float4 v = src4[j];
        float q0 = fminf(fmaxf(rintf(v.x * rs) + z, -128.0f), 127.0f);
        float q1 = fminf(fmaxf(rintf(v.y * rs) + z, -128.0f), 127.0f);
        float q2 = fminf(fmaxf(rintf(v.z * rs) + z, -128.0f), 127.0f);
        float q3 = fminf(fmaxf(rintf(v.w * rs) + z, -128.0f), 127.0f);
        acc += (int)q0 + (int)q1 + (int)q2 + (int)q3;
        __nv_bfloat162 ab, cd;
        ab.x = __float2bfloat16(q0); ab.y = __float2bfloat16(q1);
        cd.x = __float2bfloat16(q2); cd.y = __float2bfloat16(q3);
        d2[j * 2]     = ab;
        d2[j * 2 + 1] = cd;
    }
    #pragma unroll
    for (int o = 16; o; o >>= 1) acc += __shfl_xor_sync(0xFFFFFFFFu, acc, o);
    __shared__ int sacc[8];
    int lane = threadIdx.x & 31, wid = threadIdx.x >> 5;
    if (lane == 0) sacc[wid] = acc;
    __syncthreads();
    if (wid == 0) {
        acc = (lane < 8) ? sacc[lane] : 0;
        #pragma unroll
        for (int o = 4; o; o >>= 1) acc += __shfl_xor_sync(0xFFFFFFFFu, acc, o);
        if (lane == 0) rsum[row] = acc;
    }
}

// corrM[m] = s*(K*zx*zw - zw*rsx[m]) ; corrN[n] = bias[n] - s*zx*rsw[n]
__global__ void corr_kernel(const float* __restrict__ bias) {
    const int i = blockIdx.x * blockDim.x + threadIdx.x;
    const double sd  = (double)g_qp[4];
    const double zxd = (double)g_qp[1];
    const double zwd = (double)g_qp[3];
    if (i < M_DIM)
        g_cm[i] = (float)(sd * (g_kzz - zwd * (double)g_rsx[i]));
    if (i < N_DIM)
        g_cn[i] = (float)((double)bias[i] - sd * zxd * (double)g_rsw[i]);
}

// ============================================================================
// bf16 HMMA GEMM (R12 config — best known): CTA tile 128x256, BK=128 (256B rows).
// 16 warps (512 thr): 2 (M) x 8 (N), warp tile 64x32. 2-stage cp.async ring.
// ROWB=272: stride = 68 words = 4 (mod 32) -> conflict-free ldmatrix.
// ============================================================================
#define ROWB   272
#define TILE_A (128 * ROWB)                 // 34816
#define TILE_B (256 * ROWB)                 // 69632
#define STAGEB (TILE_A + TILE_B)            // 104448
#define GEMM_SMEM (2 * STAGEB)              // 208896
#define NKT (K_DIM / 128)                   // 32

__device__ __forceinline__ void fill_stage(uint32_t sbase,
                                           const char* __restrict__ Agc,
                                           const char* __restrict__ Bgc,
                                           int kt, int tid) {
    const int kOffB = kt * 256;
    const int rowStride = K_DIM * 2;
    // A: 128 rows x 16 chunks = 2048 -> 4 per thread
    #pragma unroll
    for (int i = 0; i < 4; i++) {
        const int ch = tid + i * 512;
        const int row = ch >> 4, c = (ch & 15) * 16;
        unsigned long long src = __cvta_generic_to_global(Agc + (size_t)row * rowStride + kOffB + c);
        CP_ASYNC16(sbase + row * ROWB + c, src);
    }
    // B: 256 rows x 16 chunks = 4096 -> 8 per thread
    #pragma unroll
    for (int i = 0; i < 8; i++) {
        const int ch = tid + i * 512;
        const int row = ch >> 4, c = (ch & 15) * 16;
        unsigned long long src = __cvta_generic_to_global(Bgc + (size_t)row * rowStride + kOffB + c);
        CP_ASYNC16(sbase + TILE_A + row * ROWB + c, src);
    }
}

__global__ __launch_bounds__(512, 1) void gemm_bf16_kernel(float* __restrict__ out) {
    extern __shared__ char smem[];
    const uint32_t sm = smem_u32(smem);
    const int tid = threadIdx.x;
    const int wid = tid >> 5, lane = tid & 31;
    const int warp_m = wid & 1;     // 2 warps over M: 64 rows each
    const int warp_n = wid >> 1;    // 8 warps over N: 32 cols each

    const int m0 = blockIdx.y * 128;
    const int n0 = blockIdx.x * 256;
    const char* Agc = (const char*)(g_qx + (size_t)m0 * K_DIM);
    const char* Bgc = (const char*)(g_qw + (size_t)n0 * K_DIM);

    const int l7 = lane & 7;
    const uint32_t a_lane = (uint32_t)((l7 + ((lane >> 3) & 1) * 8) * ROWB + ((lane >> 4) << 4));
    const uint32_t b_lane = (uint32_t)((l7 + ((lane >> 4) & 1) * 8) * ROWB + (((lane >> 3) & 1) << 4));

    float c[4][4][4];
    #pragma unroll
    for (int i = 0; i < 4; i++)
        #pragma unroll
        for (int j = 0; j < 4; j++)
            #pragma unroll
            for (int e = 0; e < 4; e++) c[i][j][e] = 0.0f;

    fill_stage(sm, Agc, Bgc, 0, tid);
    CP_COMMIT();

    for (int kt = 0; kt < NKT; kt++) {
        const int cs = kt & 1;
        asm volatile("cp.async.wait_group 0;" ::: "memory");   // only G_kt pending here
        __syncthreads();    // compute(kt-1) done on stage cs^1 + stage cs data visible

        if (kt + 1 < NKT) {
            fill_stage(sm + (cs ^ 1) * STAGEB, Agc, Bgc, kt + 1, tid);
            CP_COMMIT();    // overlaps with compute below
        }

        const uint32_t sb = sm + cs * STAGEB;
        const uint32_t aT = sb + (uint32_t)(warp_m * 64) * ROWB + a_lane;
        const uint32_t bT = sb + TILE_A + (uint32_t)(warp_n * 32) * ROWB + b_lane;

        #pragma unroll
        for (int ks = 0; ks < 8; ks++) {
            uint32_t a[4][4];
            #pragma unroll
            for (int mf = 0; mf < 4; mf++)
                LDM_X4(a[mf][0], a[mf][1], a[mf][2], a[mf][3],
                       aT + (uint32_t)(mf * 16) * ROWB + ks * 32);
            uint32_t b[2][4];
            #pragma unroll
            for (int nb = 0; nb < 2; nb++)
                LDM_X4(b[nb][0], b[nb][1], b[nb][2], b[nb][3],
                       bT + (uint32_t)(nb * 16) * ROWB + ks * 32);
            #pragma unroll
            for (int mf = 0; mf < 4; mf++)
                #pragma unroll
                for (int nb = 0; nb < 2; nb++) {
                    MMA_BF16(c[mf][nb * 2],     a[mf], b[nb][0], b[nb][1]);
                    MMA_BF16(c[mf][nb * 2 + 1], a[mf], b[nb][2], b[nb][3]);
                }
        }
    }

    // ---------------- fp32 epilogue: out = s*acc + corrM[m] + corrN[n] ----------------
    const float s_sc = g_qp[4];
    const int g  = lane >> 2;
    const int t2 = (lane & 3) * 2;

    #pragma unroll
    for (int mf = 0; mf < 4; mf++) {
        const int gm0 = m0 + warp_m * 64 + mf * 16 + g;
        const float cm0 = g_cm[gm0];
        const float cm1 = g_cm[gm0 + 8];
        float* r0 = out + (size_t)gm0 * N_DIM;
        float* r1 = out + (size_t)(gm0 + 8) * N_DIM;
        #pragma unroll
        for (int nf = 0; nf < 4; nf++) {
            const int gn = n0 + warp_n * 32 + nf * 8 + t2;
            const float2 cn = *(const float2*)&g_cn[gn];
            float2 o;
            o.x = fmaf(s_sc, c[mf][nf][0], cm0 + cn.x);
            o.y = fmaf(s_sc, c[mf][nf][1], cm0 + cn.y);
            *(float2*)(r0 + gn) = o;
            o.x = fmaf(s_sc, c[mf][nf][2], cm1 + cn.x);
            o.y = fmaf(s_sc, c[mf][nf][3], cm1 + cn.y);
            *(float2*)(r1 + gn) = o;
        }
    }
}

// ---------------- launch ----------------
extern "C" void kernel_launch(void* const* d_in, const int* in_sizes, int n_in,
                              void* d_out, int out_size) {
    const float* x    = (const float*)d_in[0];
    const float* W    = (const float*)d_in[1];
    const float* bias = (const float*)d_in[2];
    float* out = (float*)d_out;

    static void* mm_addr = nullptr;
    if (!mm_addr) {
        cudaFuncSetAttribute(gemm_bf16_kernel, cudaFuncAttributeMaxDynamicSharedMemorySize, GEMM_SMEM);
        cudaGetSymbolAddress(&mm_addr, g_mm);
    }

    cudaMemsetAsync(mm_addr, 0, 16);               // all 4 slots -> 0 (atomicMax targets)
    minmax2_kernel<<<3072, 256>>>(x, W);
    scales_kernel<<<1, 32>>>();
    quant_all_kernel<<<M_DIM + N_DIM, 256>>>(x, W);
    corr_kernel<<<(M_DIM + 255) / 256, 256>>>(bias);

    dim3 grid(N_DIM / 256, M_DIM / 128);   // 16 x 64 = 1024 CTAs
    gemm_bf16_kernel<<<grid, 512, GEMM_SMEM>>>(out);
}

// round 17
// speedup vs baseline: 1.0285x; 1.0051x over previous
#include <cuda_runtime.h>
#include <cuda_bf16.h>
#include <cstdint>

// Problem shape (fixed): x [4,2048,4096] -> M=8192, K=4096; W [4096,4096] (out,in)
#define M_DIM 8192
#define N_DIM 4096
#define K_DIM 4096

// ---------------- device scratch ----------------
// g_mm[0..3]: atomicMax slots (memset 0):
//   slot0 = max(~f2ord(x_min)), slot1 = max(f2ord(x_max)), slots 2/3 for W.
// g_mm[4]: block-completion ticket for the fused scales computation.
__device__ unsigned int g_mm[5];
__device__ float  g_qp[8];                               // sx, zx, sw, zw, s, invsx, invsw
__device__ double g_kzz;
__device__ __nv_bfloat16 g_qx[(size_t)M_DIM * K_DIM];    // 64 MB
__device__ __nv_bfloat16 g_qw[(size_t)N_DIM * K_DIM];    // 32 MB
__device__ float g_cm[M_DIM];                            // s*(K*zx*zw - zw*rsx[m])
__device__ float g_cn[N_DIM];                            // bias[n] - s*zx*rsw[n]

// ---------------- PTX helpers (arch-neutral, sm_80+) ----------------
__device__ __forceinline__ uint32_t smem_u32(const void* p) {
    uint32_t a;
    asm("{ .reg .u64 t; cvta.to.shared.u64 t, %1; cvt.u32.u64 %0, t; }" : "=r"(a) : "l"(p));
    return a;
}
#define CP_ASYNC16(dst, src) \
    asm volatile("cp.async.cg.shared.global [%0], [%1], 16;" :: "r"(dst), "l"(src) : "memory")
#define CP_COMMIT() asm volatile("cp.async.commit_group;" ::: "memory")

#define LDM_X4(r0, r1, r2, r3, addr) \
    asm volatile("ldmatrix.sync.aligned.m8n8.x4.shared.b16 {%0,%1,%2,%3}, [%4];" \
        : "=r"(r0), "=r"(r1), "=r"(r2), "=r"(r3) : "r"(addr))

#define MMA_BF16(c, a, b0, b1) \
    asm volatile("mma.sync.aligned.m16n8k16.row.col.f32.bf16.bf16.f32 " \
        "{%0,%1,%2,%3}, {%4,%5,%6,%7}, {%8,%9}, {%0,%1,%2,%3};" \
        : "+f"((c)[0]), "+f"((c)[1]), "+f"((c)[2]), "+f"((c)[3]) \
        : "r"((a)[0]), "r"((a)[1]), "r"((a)[2]), "r"((a)[3]), "r"(b0), "r"(b1))

// ---------------- order-preserving encode ----------------
__device__ __forceinline__ unsigned f2ord(float f) {
    unsigned u = __float_as_uint(f);
    return (u & 0x80000000u) ? ~u : (u | 0x80000000u);
}
__device__ __forceinline__ float ord2f(unsigned u) {
    unsigned b = (u & 0x80000000u) ? (u ^ 0x80000000u) : ~u;
    return __uint_as_float(b);
}

// One launch covering both tensors: blocks [0,2048) -> x, [2048,3072) -> W.
// min tracked as atomicMax of ~f2ord(v). The LAST finishing block (ticket
// pattern) computes the quantization params and writes g_qp/g_kzz.
__global__ void minmax2_kernel(const float* __restrict__ xp, const float* __restrict__ wp) {
    const int isW = (blockIdx.x >= 2048);
    const float4* p4 = (const float4*)(isW ? wp : xp);
    const int n4 = (isW ? (N_DIM * K_DIM) : (M_DIM * K_DIM)) >> 2;
    const int nb = isW ? 1024 : 2048;
    const int bix = isW ? (blockIdx.x - 2048) : blockIdx.x;
    const int slot = isW ? 2 : 0;

    float mn = 3.4e38f, mx = -3.4e38f;
    int idx = bix * blockDim.x + threadIdx.x;
    int stride = nb * blockDim.x;
    for (int i = idx; i < n4; i += stride) {
        float4 v = p4[i];
        mn = fminf(mn, fminf(fminf(v.x, v.y), fminf(v.z, v.w)));
        mx = fmaxf(mx, fmaxf(fmaxf(v.x, v.y), fmaxf(v.z, v.w)));
    }
    #pragma unroll
    for (int o = 16; o; o >>= 1) {
        mn = fminf(mn, __shfl_xor_sync(0xFFFFFFFFu, mn, o));
        mx = fmaxf(mx, __shfl_xor_sync(0xFFFFFFFFu, mx, o));
    }
    __shared__ float smn[8], smx[8];
    int lane = threadIdx.x & 31, wid = threadIdx.x >> 5;
    if (lane == 0) { smn[wid] = mn; smx[wid] = mx; }
    __syncthreads();
    if (wid == 0) {
        mn = (lane < (blockDim.x >> 5)) ? smn[lane] : 3.4e38f;
        mx = (lane < (blockDim.x >> 5)) ? smx[lane] : -3.4e38f;
        #pragma unroll
        for (int o = 4; o; o >>= 1) {
            mn = fminf(mn, __shfl_xor_sync(0xFFFFFFFFu, mn, o));
            mx = fmaxf(mx, __shfl_xor_sync(0xFFFFFFFFu, mx, o));
        }
        if (lane == 0) {
            atomicMax(&g_mm[slot],     ~f2ord(mn));
            atomicMax(&g_mm[slot + 1],  f2ord(mx));
            __threadfence();
            unsigned t = atomicAdd(&g_mm[4], 1u);
            if (t == 3071u) {              // last block: all slots final
                __threadfence();
                unsigned m0 = atomicMax(&g_mm[0], 0u);   // atomic reads
                unsigned m1 = atomicMax(&g_mm[1], 0u);
                unsigned m2 = atomicMax(&g_mm[2], 0u);
                unsigned m3 = atomicMax(&g_mm[3], 0u);
                float xmn = ord2f(~m0), xmx = ord2f(m1);
                float wmn = ord2f(~m2), wmx = ord2f(m3);
                float sx = (xmx - xmn) / 255.0f;
                float zx = rintf(-128.0f - xmn / sx);
                float sw = (wmx - wmn) / 255.0f;
                float zw = rintf(-128.0f - wmn / sw);
                g_qp[0] = sx; g_qp[1] = zx; g_qp[2] = sw; g_qp[3] = zw;
                g_qp[4] = sx * sw;
                g_qp[5] = 1.0f / sx;
                g_qp[6] = 1.0f / sw;
                g_kzz = (double)zx * (double)zw * (double)K_DIM;
                __threadfence();
            }
        }
    }
}

// quantize fp32 -> bf16-exact integer; per-row correction computed in-place
// (corr kernel eliminated — identical fp64 expressions, identical results).
// 256 threads/block, K=4096 -> exactly 4 unrolled float4 iterations per thread.
__global__ __launch_bounds__(256) void quant_all_kernel(const float* __restrict__ xp,
                                                        const float* __restrict__ wp,
                                                        const float* __restrict__ bias) {
    const int which = (blockIdx.x >= M_DIM);
    const int row = which ? (blockIdx.x - M_DIM) : blockIdx.x;
    const float rs = g_qp[which ? 6 : 5];
    const float z  = g_qp[which ? 3 : 1];
    const float* src = which ? wp : xp;
    __nv_bfloat16* dst = which ? g_qw : g_qx;

    const float4* src4 = (const float4*)(src + (size_t)row * K_DIM);
    __nv_bfloat162* d2 = (__nv_bfloat162*)(dst + (size_t)row * K_DIM);
    int acc = 0;
    #pragma unroll
    for (int it = 0; it < 4; it++) {
        const int j = threadIdx.x + it * 256;
        float4 v = src4[j];
        float q0 = fminf(fmaxf(rintf(v.x * rs) + z, -128.0f), 127.0f);
        float q1 = fminf(fmaxf(rintf(v.y * rs) + z, -128.0f), 127.0f);
        float q2 = fminf(fmaxf(rintf(v.z * rs) + z, -128.0f), 127.0f);
        float q3 = fminf(fmaxf(rintf(v.w * rs) + z, -128.0f), 127.0f);
        acc += (int)q0 + (int)q1 + (int)q2 + (int)q3;
        __nv_bfloat162 ab, cd;
        ab.x = __float2bfloat16(q0); ab.y = __float2bfloat16(q1);
        cd.x = __float2bfloat16(q2); cd.y = __float2bfloat16(q3);
        d2[j * 2]     = ab;
        d2[j * 2 + 1] = cd;
    }
    #pragma unroll
    for (int o = 16; o; o >>= 1) acc += __shfl_xor_sync(0xFFFFFFFFu, acc, o);
    __shared__ int sacc[8];
    int lane = threadIdx.x & 31, wid = threadIdx.x >> 5;
    if (lane == 0) sacc[wid] = acc;
    __syncthreads();
    if (wid == 0) {
        acc = (lane < 8) ? sacc[lane] : 0;
        #pragma unroll
        for (int o = 4; o; o >>= 1) acc += __shfl_xor_sync(0xFFFFFFFFu, acc, o);
        if (lane == 0) {
            const double sd  = (double)g_qp[4];
            if (which) {
                const double zxd = (double)g_qp[1];
                g_cn[row] = (float)((double)bias[row] - sd * zxd * (double)acc);
            } else {
                const double zwd = (double)g_qp[3];
                g_cm[row] = (float)(sd * (g_kzz - zwd * (double)acc));
            }
        }
    }
}

// ============================================================================
// bf16 HMMA GEMM (R12/R14 config — best known): CTA tile 128x256, BK=128.
// 16 warps (512 thr): 2 (M) x 8 (N), warp tile 64x32. 2-stage cp.async ring.
// ROWB=272: stride = 68 words = 4 (mod 32) -> conflict-free ldmatrix.
// ============================================================================
#define ROWB   272
#define TILE_A (128 * ROWB)                 // 34816
#define TILE_B (256 * ROWB)                 // 69632
#define STAGEB (TILE_A + TILE_B)            // 104448
#define GEMM_SMEM (2 * STAGEB)              // 208896
#define NKT (K_DIM / 128)                   // 32

__device__ __forceinline__ void fill_stage(uint32_t sbase,
                                           const char* __restrict__ Agc,
                                           const char* __restrict__ Bgc,
                                           int kt, int tid) {
    const int kOffB = kt * 256;
    const int rowStride = K_DIM * 2;
    // A: 128 rows x 16 chunks = 2048 -> 4 per thread
    #pragma unroll
    for (int i = 0; i < 4; i++) {
        const int ch = tid + i * 512;
        const int row = ch >> 4, c = (ch & 15) * 16;
        unsigned long long src = __cvta_generic_to_global(Agc + (size_t)row * rowStride + kOffB + c);
        CP_ASYNC16(sbase + row * ROWB + c, src);
    }
    // B: 256 rows x 16 chunks = 4096 -> 8 per thread
    #pragma unroll
    for (int i = 0; i < 8; i++) {
        const int ch = tid + i * 512;
        const int row = ch >> 4, c = (ch & 15) * 16;
        unsigned long long src = __cvta_generic_to_global(Bgc + (size_t)row * rowStride + kOffB + c);
        CP_ASYNC16(sbase + TILE_A + row * ROWB + c, src);
    }
}

__global__ __launch_bounds__(512, 1) void gemm_bf16_kernel(float* __restrict__ out) {
    extern __shared__ char smem[];
    const uint32_t sm = smem_u32(smem);
    const int tid = threadIdx.x;
    const int wid = tid >> 5, lane = tid & 31;
    const int warp_m = wid & 1;     // 2 warps over M: 64 rows each
    const int warp_n = wid >> 1;    // 8 warps over N: 32 cols each

    const int m0 = blockIdx.y * 128;
    const int n0 = blockIdx.x * 256;
    const char* Agc = (const char*)(g_qx + (size_t)m0 * K_DIM);
    const char* Bgc = (const char*)(g_qw + (size_t)n0 * K_DIM);

    const int l7 = lane & 7;
    const uint32_t a_lane = (uint32_t)((l7 + ((lane >> 3) & 1) * 8) * ROWB + ((lane >> 4) << 4));
    const uint32_t b_lane = (uint32_t)((l7 + ((lane >> 4) & 1) * 8) * ROWB + (((lane >> 3) & 1) << 4));

    float c[4][4][4];
    #pragma unroll
    for (int i = 0; i < 4; i++)
        #pragma unroll
        for (int j = 0; j < 4; j++)
            #pragma unroll
            for (int e = 0; e < 4; e++) c[i][j][e] = 0.0f;

    fill_stage(sm, Agc, Bgc, 0, tid);
    CP_COMMIT();

    for (int kt = 0; kt < NKT; kt++) {
        const int cs = kt & 1;
        asm volatile("cp.async.wait_group 0;" ::: "memory");   // only G_kt pending here
        __syncthreads();    // compute(kt-1) done on stage cs^1 + stage cs data visible

        if (kt + 1 < NKT) {
            fill_stage(sm + (cs ^ 1) * STAGEB, Agc, Bgc, kt + 1, tid);
            CP_COMMIT();    // overlaps with compute below
        }

        const uint32_t sb = sm + cs * STAGEB;
        const uint32_t aT = sb + (uint32_t)(warp_m * 64) * ROWB + a_lane;
        const uint32_t bT = sb + TILE_A + (uint32_t)(warp_n * 32) * ROWB + b_lane;

        #pragma unroll
        for (int ks = 0; ks < 8; ks++) {
            uint32_t a[4][4];
            #pragma unroll
            for (int mf = 0; mf < 4; mf++)
                LDM_X4(a[mf][0], a[mf][1], a[mf][2], a[mf][3],
                       aT + (uint32_t)(mf * 16) * ROWB + ks * 32);
            uint32_t b[2][4];
            #pragma unroll
            for (int nb = 0; nb < 2; nb++)
                LDM_X4(b[nb][0], b[nb][1], b[nb][2], b[nb][3],
                       bT + (uint32_t)(nb * 16) * ROWB + ks * 32);
            #pragma unroll
            for (int mf = 0; mf < 4; mf++)
                #pragma unroll
                for (int nb = 0; nb < 2; nb++) {
                    MMA_BF16(c[mf][nb * 2],     a[mf], b[nb][0], b[nb][1]);
                    MMA_BF16(c[mf][nb * 2 + 1], a[mf], b[nb][2], b[nb][3]);
                }
        }
    }

    // ---------------- fp32 epilogue: out = s*acc + corrM[m] + corrN[n] ----------------
    const float s_sc = g_qp[4];
    const int g  = lane >> 2;
    const int t2 = (lane & 3) * 2;

    #pragma unroll
    for (int mf = 0; mf < 4; mf++) {
        const int gm0 = m0 + warp_m * 64 + mf * 16 + g;
        const float cm0 = g_cm[gm0];
        const float cm1 = g_cm[gm0 + 8];
        float* r0 = out + (size_t)gm0 * N_DIM;
        float* r1 = out + (size_t)(gm0 + 8) * N_DIM;
        #pragma unroll
        for (int nf = 0; nf < 4; nf++) {
            const int gn = n0 + warp_n * 32 + nf * 8 + t2;
            const float2 cn = *(const float2*)&g_cn[gn];
            float2 o;
            o.x = fmaf(s_sc, c[mf][nf][0], cm0 + cn.x);
            o.y = fmaf(s_sc, c[mf][nf][1], cm0 + cn.y);
            *(float2*)(r0 + gn) = o;
            o.x = fmaf(s_sc, c[mf][nf][2], cm1 + cn.x);
            o.y = fmaf(s_sc, c[mf][nf][3], cm1 + cn.y);
            *(float2*)(r1 + gn) = o;
        }
    }
}

// ---------------- launch ----------------
extern "C" void kernel_launch(void* const* d_in, const int* in_sizes, int n_in,
                              void* d_out, int out_size) {
    const float* x    = (const float*)d_in[0];
    const float* W    = (const float*)d_in[1];
    const float* bias = (const float*)d_in[2];
    float* out = (float*)d_out;

    static void* mm_addr = nullptr;
    if (!mm_addr) {
        cudaFuncSetAttribute(gemm_bf16_kernel, cudaFuncAttributeMaxDynamicSharedMemorySize, GEMM_SMEM);
        cudaGetSymbolAddress(&mm_addr, g_mm);
    }

    cudaMemsetAsync(mm_addr, 0, 20);               // 4 slots + ticket -> 0
    minmax2_kernel<<<3072, 256>>>(x, W);           // last block writes g_qp/g_kzz
    quant_all_kernel<<<M_DIM + N_DIM, 256>>>(x, W, bias);

    dim3 grid(N_DIM / 256, M_DIM / 128);   // 16 x 64 = 1024 CTAs
    gemm_bf16_kernel<<<grid, 512, GEMM_SMEM>>>(out);
}